// round 13
// baseline (speedup 1.0000x reference)
#include <cuda_runtime.h>
#include <cstdint>
#include <cstddef>

// ---------------------------------------------------------------------------
// CrossAttentionDecoder: B=1024 (8*128), n_tok=16, num_latents=128, d=512,
// heads=8, dh=64.  Mask: batch b attends only to latents j <= (b % 128).
//
// Fully-fused, one CTA per batch b (512 threads), superchunked d-loop.
// R13: weight b-fragments re-laid so each lane's 4 nt-fragments are
// contiguous (2x LDG.128 per k-step) and consumed through register
// prefetch rings (depth 4 for the 64-iter projections, depth 2 for the
// 8-iter phase-A/ov loops) to cover L2 latency.
// ---------------------------------------------------------------------------

#define DIMK 512

// layouts: g_Wqf/g_Wvf/g_Wof: [n4 16][kk 64][lane 32][nt 4][2]
//          g_Wkf:             [h 8][ntg4 16][ks 8][lane 32][nt 4][2]
__device__ float g_Wqf[16 * 64 * 32 * 8];
__device__ float g_Wvf[16 * 64 * 32 * 8];
__device__ float g_Wof[16 * 64 * 32 * 8];
__device__ float g_Wkf[8 * 16 * 8 * 32 * 8];

// ---------------- helpers ---------------------------------------------------
__device__ __forceinline__ float to_tf32(float x) {
    uint32_t u; asm("cvt.rna.tf32.f32 %0, %1;" : "=r"(u) : "f"(x));
    return __uint_as_float(u);
}
__device__ __forceinline__ uint32_t f2u(float x) { return __float_as_uint(x); }

__device__ __forceinline__ void mma_tf32(float* d, const uint32_t* a, const uint32_t* b) {
    asm volatile(
        "mma.sync.aligned.m16n8k8.row.col.f32.tf32.tf32.f32 "
        "{%0,%1,%2,%3}, {%4,%5,%6,%7}, {%8,%9}, {%0,%1,%2,%3};\n"
        : "+f"(d[0]), "+f"(d[1]), "+f"(d[2]), "+f"(d[3])
        : "r"(a[0]), "r"(a[1]), "r"(a[2]), "r"(a[3]),
          "r"(b[0]), "r"(b[1]));
}

// ---------------------------------------------------------------------------
// prep_w: fragment-pack Wq, Wv, Wo and Wk (transposed) into lane-contiguous
// nt-quad layout.
// ---------------------------------------------------------------------------
__global__ __launch_bounds__(256)
void prep_w(const float* __restrict__ Wq, const float* __restrict__ Wk,
            const float* __restrict__ Wv, const float* __restrict__ Wo)
{
    int gid = blockIdx.x * 256 + threadIdx.x;        // 2048 blocks
    int lane = gid & 31, kk = (gid >> 5) & 63, nv = gid >> 11;   // nv 0..255
    int g = lane >> 2, tg = lane & 3;
    if (nv < 192) {
        const float* W; float* dst; int dn;
        if (nv < 64)       { W = Wq; dst = g_Wqf; dn = nv; }
        else if (nv < 128) { W = Wv; dst = g_Wvf; dn = nv - 64; }
        else               { W = Wo; dst = g_Wof; dn = nv - 128; }
        float v0 = to_tf32(W[(size_t)(dn * 8 + g) * DIMK + kk * 8 + tg]);
        float v1 = to_tf32(W[(size_t)(dn * 8 + g) * DIMK + kk * 8 + tg + 4]);
        *(float2*)(dst + (size_t)((((dn >> 2) * 64 + kk) * 32 + lane) * 4 + (dn & 3)) * 2) =
            make_float2(v0, v1);
    } else {
        int t = nv - 192;            // 0..63
        int h = t >> 3, ks = t & 7;
        int ntg = kk;
        float v0 = to_tf32(Wk[(size_t)(h * 64 + ks * 8 + tg) * DIMK + ntg * 8 + g]);
        float v1 = to_tf32(Wk[(size_t)(h * 64 + ks * 8 + tg + 4) * DIMK + ntg * 8 + g]);
        *(float2*)(g_Wkf + (size_t)(((((h * 16 + (ntg >> 2)) * 8 + ks) * 32 + lane) * 4 +
                                     (ntg & 3)) * 2)) = make_float2(v0, v1);
    }
}

// ---------------------------------------------------------------------------
// fattn7: one CTA per batch b (heavy-first order), 512 threads (16 warps).
// Smem (floats): R 16384 (qf pass1 / Pf after) | qkc 16384 | lc 17408
// ---------------------------------------------------------------------------
#define F7_R   0
#define F7_QKC 16384
#define F7_LC  32768
#define F7_TOT 50176

__global__ __launch_bounds__(512, 1)
void fattn7(const float* __restrict__ x, const float* __restrict__ l,
            const float* __restrict__ bo, float* __restrict__ out)
{
    extern __shared__ __align__(16) float sm[];
    float* qf  = sm + F7_R;      // pass1: q a-frags [8h][8ks][128]
    float* Pf  = sm + F7_R;      // post-pass1: P a-frags [8mt][16ksj][128]
    float* qkc = sm + F7_QKC;    // qk/pl a-frags [8mt][16ksd][128]; also x/ov frags
    float* lc  = sm + F7_LC;     // l tiles [jt16][dtile16] x 68

    const int bid = blockIdx.x;
    const int b = (bid & 7) * 128 + (127 - (bid >> 3));   // heavy-first
    const int nj = (b & 127) + 1;
    const int T = (nj + 7) >> 3;
    const int njc8 = T << 3;

    const int tid = threadIdx.x, w = tid >> 5, lane = tid & 31;
    const int g = lane >> 2, tg = lane & 3;
    const int wm = w >> 2, wn = w & 3;        // scores mapping
    const int amt = w >> 1, anh = w & 1;      // phase A / pass2 / ov mapping

    // conflict-free lc tile read offsets (R8-verified)
    const int p1o0 = g * 4 + tg;
    const int p1o1 = ((g ^ 4) + 8) * 4 + tg;
    const int h2 = g >> 2, gl = g & 3;
    const int p2o0 = ((tg ^ (h2 << 2)) + (h2 << 3)) * 4 + gl;
    const int p2o1 = (((tg + 4) ^ (h2 << 2)) + (h2 << 3)) * 4 + gl;

    // ============ prologue: stage x a-frags into qkc ============
    #pragma unroll
    for (int it = 0; it < 4; it++) {
        int idx = tid + it * 512;           // 0..2047
        int i = idx >> 7, c4 = (idx & 127) * 4;
        float4 v = *(const float4*)(x + ((size_t)(b * 16 + i)) * 512 + c4);
        float vv[4] = {v.x, v.y, v.z, v.w};
        #pragma unroll
        for (int e = 0; e < 4; e++) {
            int c = c4 + e;
            qkc[(c >> 3) * 128 + ((i & 7) * 4 + (c & 3)) * 4 +
                ((i >> 3) + 2 * ((c >> 2) & 1))] = to_tf32(vv[e]);
        }
    }
    __syncthreads();

    // ============ Q-proj: q = x @ Wq^T -> qf (ring depth 4) ============
    {
        float acc[4][4];
        #pragma unroll
        for (int nt = 0; nt < 4; nt++)
            #pragma unroll
            for (int c = 0; c < 4; c++) acc[nt][c] = 0.f;
        const float* wqb = g_Wqf + (size_t)w * 64 * 256 + lane * 8;
        uint4 r0[4], r1[4];
        #pragma unroll
        for (int p = 0; p < 4; p++) {
            r0[p] = *(const uint4*)(wqb + p * 256);
            r1[p] = *(const uint4*)(wqb + p * 256 + 4);
        }
        #pragma unroll 4
        for (int kk = 0; kk < 64; kk++) {
            float4 af = *(const float4*)(qkc + kk * 128 + lane * 4);
            uint4 b0 = r0[kk & 3], b1 = r1[kk & 3];
            if (kk + 4 < 64) {
                r0[kk & 3] = *(const uint4*)(wqb + (kk + 4) * 256);
                r1[kk & 3] = *(const uint4*)(wqb + (kk + 4) * 256 + 4);
            }
            uint32_t a[4] = {f2u(af.x), f2u(af.y), f2u(af.z), f2u(af.w)};
            uint32_t bu[4][2] = {{b0.x, b0.y}, {b0.z, b0.w}, {b1.x, b1.y}, {b1.z, b1.w}};
            #pragma unroll
            for (int nt = 0; nt < 4; nt++)
                mma_tf32(acc[nt], a, bu[nt]);
        }
        __syncthreads();   // qkc (x-frags) dead after all warps' reads
        #pragma unroll
        for (int nt = 0; nt < 4; nt++) {
            int c0 = w * 32 + nt * 8 + 2 * tg;
            #pragma unroll
            for (int e = 0; e < 4; e++) {
                int r = g + ((e >> 1) << 3);
                int c = c0 + (e & 1);
                int h = c >> 6, ks = (c & 63) >> 3;
                qf[(h * 8 + ks) * 128 + (g * 4 + (c & 3)) * 4 +
                   ((r >> 3) + 2 * ((c >> 2) & 1))] = to_tf32(acc[nt][e]);
            }
        }
    }
    __syncthreads();

    float sacc[2][4][4];
    #pragma unroll
    for (int i = 0; i < 2; i++)
        #pragma unroll
        for (int j = 0; j < 4; j++)
            #pragma unroll
            for (int c = 0; c < 4; c++) sacc[i][j][c] = 0.f;

    // ================= pass 1: scores, 4 superchunks of 128 d =================
    for (int ch2 = 0; ch2 < 4; ch2++) {
        #pragma unroll
        for (int sub = 0; sub < 2; sub++) {
            const int d0 = ch2 * 128 + sub * 64;
            // l loads first; phase A overlaps the latency
            float4 sv[4];
            #pragma unroll
            for (int it = 0; it < 4; it++) {
                int i4 = tid + it * 512;
                int j = i4 >> 4, dq = i4 & 15;
                sv[it] = make_float4(0.f, 0.f, 0.f, 0.f);
                if (j < nj)
                    sv[it] = *(const float4*)(l + ((size_t)(b * 128 + j)) * 512 + d0 + dq * 4);
            }
            // phase A: qk d-cols [d0, d0+64) for head amt (ring depth 2)
            float aacc[4][4];
            #pragma unroll
            for (int nt = 0; nt < 4; nt++)
                #pragma unroll
                for (int c = 0; c < 4; c++) aacc[nt][c] = 0.f;
            {
                const float* wkb = g_Wkf +
                    (size_t)((amt * 16 + ch2 * 4 + sub * 2 + anh) * 8) * 256 + lane * 8;
                uint4 r0[2], r1[2];
                #pragma unroll
                for (int p = 0; p < 2; p++) {
                    r0[p] = *(const uint4*)(wkb + p * 256);
                    r1[p] = *(const uint4*)(wkb + p * 256 + 4);
                }
                #pragma unroll
                for (int ks = 0; ks < 8; ks++) {
                    float4 ac = *(const float4*)(qf + (amt * 8 + ks) * 128 + lane * 4);
                    uint4 b0 = r0[ks & 1], b1 = r1[ks & 1];
                    if (ks + 2 < 8) {
                        r0[ks & 1] = *(const uint4*)(wkb + (ks + 2) * 256);
                        r1[ks & 1] = *(const uint4*)(wkb + (ks + 2) * 256 + 4);
                    }
                    uint32_t a[4] = {f2u(ac.x), f2u(ac.y), f2u(ac.z), f2u(ac.w)};
                    uint32_t bu[4][2] = {{b0.x, b0.y}, {b0.z, b0.w}, {b1.x, b1.y}, {b1.z, b1.w}};
                    #pragma unroll
                    for (int nt = 0; nt < 4; nt++)
                        mma_tf32(aacc[nt], a, bu[nt]);
                }
            }
            // scatter qk-half into qkc a-frags (superchunk ksd = sub*8 + ..)
            #pragma unroll
            for (int nt = 0; nt < 4; nt++) {
                int c0 = anh * 32 + nt * 8 + 2 * tg;
                #pragma unroll
                for (int e = 0; e < 4; e++) {
                    int c = c0 + (e & 1);
                    qkc[((amt * 16 + sub * 8 + (c >> 3)) * 32 + g * 4 + (c & 3)) * 4 +
                        ((e >> 1) + 2 * ((c >> 2) & 1))] = to_tf32(aacc[nt][e]);
                }
            }
            // lc STS (tiles [jt][sub*8 + dtile])
            #pragma unroll
            for (int it = 0; it < 4; it++) {
                int i4 = tid + it * 512;
                int j = i4 >> 4, dq = i4 & 15;
                if (j < njc8) {
                    int hh = dq & 1;
                    int X = ((j & 7) ^ (hh << 2)) + (hh << 3);
                    float4 o;
                    o.x = to_tf32(sv[it].x); o.y = to_tf32(sv[it].y);
                    o.z = to_tf32(sv[it].z); o.w = to_tf32(sv[it].w);
                    *(float4*)(lc + ((j >> 3) * 16 + sub * 8 + (dq >> 1)) * 68 + X * 4) = o;
                }
            }
        }
        __syncthreads();

        // scores mma over 16 d-tiles
        #pragma unroll
        for (int ksd = 0; ksd < 16; ksd++) {
            float4 af0 = *(const float4*)(qkc + ((wm * 2 + 0) * 16 + ksd) * 128 + lane * 4);
            float4 af1 = *(const float4*)(qkc + ((wm * 2 + 1) * 16 + ksd) * 128 + lane * 4);
            uint32_t a0[4] = {f2u(af0.x), f2u(af0.y), f2u(af0.z), f2u(af0.w)};
            uint32_t a1[4] = {f2u(af1.x), f2u(af1.y), f2u(af1.z), f2u(af1.w)};
            #pragma unroll
            for (int jt4 = 0; jt4 < 4; jt4++) {
                int jt = wn + jt4 * 4;
                if (jt < T) {
                    int tb = (jt * 16 + ksd) * 68;
                    uint32_t bu[2] = { f2u(lc[tb + p1o0]), f2u(lc[tb + p1o1]) };
                    mma_tf32(sacc[0][jt4], a0, bu);
                    mma_tf32(sacc[1][jt4], a1, bu);
                }
            }
        }
        __syncthreads();
    }

    // ---- scatter scores -> Pf (a-frag layout, scaled); Pf overlays dead qf ----
    #pragma unroll
    for (int mt = 0; mt < 2; mt++) {
        #pragma unroll
        for (int jt4 = 0; jt4 < 4; jt4++) {
            int jt = wn + jt4 * 4;
            if (jt < T) {
                #pragma unroll
                for (int e = 0; e < 4; e++) {
                    int j = jt * 8 + 2 * tg + (e & 1);
                    Pf[((wm * 2 + mt) * 16 + jt) * 128 + (g * 4 + (j & 3)) * 4 +
                       ((e >> 1) + 2 * ((j >> 2) & 1))] = sacc[mt][jt4][e] * 0.125f;
                }
            }
        }
    }
    __syncthreads();

    // ---- softmax: warp w owns rows w*8 .. w*8+7 (packed-frag addressing) ----
    #pragma unroll
    for (int rr = 0; rr < 8; rr++) {
        int row = w * 8 + rr;
        int mt = row >> 4, rl = row & 15;
        int base = mt * 16 * 128 + ((rl & 7) * 4) * 4 + (rl >> 3);
        float mx = -1e30f;
        for (int j = lane; j < nj; j += 32)
            mx = fmaxf(mx, Pf[base + (j >> 3) * 128 + (j & 3) * 4 + 2 * ((j >> 2) & 1)]);
        #pragma unroll
        for (int o = 16; o; o >>= 1) mx = fmaxf(mx, __shfl_xor_sync(0xffffffffu, mx, o));
        float e4[4]; int cnt = 0; float s = 0.f;
        for (int j = lane; j < nj; j += 32) {
            float ev = __expf(Pf[base + (j >> 3) * 128 + (j & 3) * 4 + 2 * ((j >> 2) & 1)] - mx);
            e4[cnt++] = ev; s += ev;
        }
        #pragma unroll
        for (int o = 16; o; o >>= 1) s += __shfl_xor_sync(0xffffffffu, s, o);
        float inv = 1.f / s;
        cnt = 0;
        for (int j = lane; j < njc8; j += 32) {
            float val = (j < nj) ? e4[cnt++] * inv : 0.f;
            Pf[base + (j >> 3) * 128 + (j & 3) * 4 + 2 * ((j >> 2) & 1)] = to_tf32(val);
        }
    }

    // ================= pass 2: pl + ov, 4 superchunks =================
    float ovacc[4][4];
    #pragma unroll
    for (int nt = 0; nt < 4; nt++)
        #pragma unroll
        for (int c = 0; c < 4; c++) ovacc[nt][c] = 0.f;

    for (int ch2 = 0; ch2 < 4; ch2++) {
        #pragma unroll
        for (int sub = 0; sub < 2; sub++) {
            const int d0 = ch2 * 128 + sub * 64;
            float4 sv[4];
            #pragma unroll
            for (int it = 0; it < 4; it++) {
                int i4 = tid + it * 512;
                int j = i4 >> 4, dq = i4 & 15;
                sv[it] = make_float4(0.f, 0.f, 0.f, 0.f);
                if (j < nj)
                    sv[it] = *(const float4*)(l + ((size_t)(b * 128 + j)) * 512 + d0 + dq * 4);
            }
            // ov for previous superchunk, half 'sub' (ring depth 2, overlaps loads)
            if (ch2 > 0) {
                const int kkb = (ch2 - 1) * 16 + sub * 8;
                const float* wvb = g_Wvf +
                    ((size_t)(amt * 2 + anh) * 64 + kkb) * 256 + lane * 8;
                uint4 r0[2], r1[2];
                #pragma unroll
                for (int p = 0; p < 2; p++) {
                    r0[p] = *(const uint4*)(wvb + p * 256);
                    r1[p] = *(const uint4*)(wvb + p * 256 + 4);
                }
                #pragma unroll
                for (int ksd = 0; ksd < 8; ksd++) {
                    float4 af = *(const float4*)(qkc +
                        ((amt * 16 + sub * 8 + ksd)) * 128 + lane * 4);
                    uint4 b0 = r0[ksd & 1], b1 = r1[ksd & 1];
                    if (ksd + 2 < 8) {
                        r0[ksd & 1] = *(const uint4*)(wvb + (ksd + 2) * 256);
                        r1[ksd & 1] = *(const uint4*)(wvb + (ksd + 2) * 256 + 4);
                    }
                    uint32_t a[4] = {f2u(af.x), f2u(af.y), f2u(af.z), f2u(af.w)};
                    uint32_t bu[4][2] = {{b0.x, b0.y}, {b0.z, b0.w}, {b1.x, b1.y}, {b1.z, b1.w}};
                    #pragma unroll
                    for (int nt = 0; nt < 4; nt++)
                        mma_tf32(ovacc[nt], a, bu[nt]);
                }
            }
            // lc STS
            #pragma unroll
            for (int it = 0; it < 4; it++) {
                int i4 = tid + it * 512;
                int j = i4 >> 4, dq = i4 & 15;
                if (j < njc8) {
                    int hh = dq & 1;
                    int X = ((j & 7) ^ (hh << 2)) + (hh << 3);
                    float4 o;
                    o.x = to_tf32(sv[it].x); o.y = to_tf32(sv[it].y);
                    o.z = to_tf32(sv[it].z); o.w = to_tf32(sv[it].w);
                    *(float4*)(lc + ((j >> 3) * 16 + sub * 8 + (dq >> 1)) * 68 + X * 4) = o;
                }
            }
        }
        __syncthreads();

        // pl over both halves -> qkc
        #pragma unroll
        for (int sub = 0; sub < 2; sub++) {
            float placc[4][4];
            #pragma unroll
            for (int nt = 0; nt < 4; nt++)
                #pragma unroll
                for (int c = 0; c < 4; c++) placc[nt][c] = 0.f;
            for (int ksj = 0; ksj < T; ksj++) {
                float4 af = *(const float4*)(Pf + (amt * 16 + ksj) * 128 + lane * 4);
                uint32_t a[4] = {f2u(af.x), f2u(af.y), f2u(af.z), f2u(af.w)};
                #pragma unroll
                for (int nt = 0; nt < 4; nt++) {
                    int tb = (ksj * 16 + sub * 8 + anh * 4 + nt) * 68;
                    uint32_t bu[2] = { f2u(lc[tb + p2o0]), f2u(lc[tb + p2o1]) };
                    mma_tf32(placc[nt], a, bu);
                }
            }
            #pragma unroll
            for (int nt = 0; nt < 4; nt++) {
                int c0 = anh * 32 + nt * 8 + 2 * tg;
                #pragma unroll
                for (int e = 0; e < 4; e++) {
                    int c = c0 + (e & 1);
                    qkc[((amt * 16 + sub * 8 + (c >> 3)) * 32 + g * 4 + (c & 3)) * 4 +
                        ((e >> 1) + 2 * ((c >> 2) & 1))] = to_tf32(placc[nt][e]);
                }
            }
        }
        __syncthreads();
    }

    // ---- final ov (superchunk 3, both halves; ring depth 2) ----
    #pragma unroll
    for (int sub = 0; sub < 2; sub++) {
        const int kkb = 48 + sub * 8;
        const float* wvb = g_Wvf + ((size_t)(amt * 2 + anh) * 64 + kkb) * 256 + lane * 8;
        uint4 r0[2], r1[2];
        #pragma unroll
        for (int p = 0; p < 2; p++) {
            r0[p] = *(const uint4*)(wvb + p * 256);
            r1[p] = *(const uint4*)(wvb + p * 256 + 4);
        }
        #pragma unroll
        for (int ksd = 0; ksd < 8; ksd++) {
            float4 af = *(const float4*)(qkc + ((amt * 16 + sub * 8 + ksd)) * 128 + lane * 4);
            uint4 b0 = r0[ksd & 1], b1 = r1[ksd & 1];
            if (ksd + 2 < 8) {
                r0[ksd & 1] = *(const uint4*)(wvb + (ksd + 2) * 256);
                r1[ksd & 1] = *(const uint4*)(wvb + (ksd + 2) * 256 + 4);
            }
            uint32_t a[4] = {f2u(af.x), f2u(af.y), f2u(af.z), f2u(af.w)};
            uint32_t bu[4][2] = {{b0.x, b0.y}, {b0.z, b0.w}, {b1.x, b1.y}, {b1.z, b1.w}};
            #pragma unroll
            for (int nt = 0; nt < 4; nt++)
                mma_tf32(ovacc[nt], a, bu[nt]);
        }
    }
    __syncthreads();   // all ov reads of qkc complete

    // ============ epilogue: ov -> a-frags, out = ov @ Wo^T + bo ============
    #pragma unroll
    for (int nt = 0; nt < 4; nt++) {
        int c0 = amt * 64 + anh * 32 + nt * 8 + 2 * tg;
        #pragma unroll
        for (int e = 0; e < 4; e++) {
            int r = g + ((e >> 1) << 3);          // token i
            int c = c0 + (e & 1);
            qkc[(c >> 3) * 128 + (g * 4 + (c & 3)) * 4 +
                ((r >> 3) + 2 * ((c >> 2) & 1))] = to_tf32(ovacc[nt][e]);
        }
    }
    __syncthreads();

    // O-proj (ring depth 4)
    {
        float acc[4][4];
        #pragma unroll
        for (int nt = 0; nt < 4; nt++)
            #pragma unroll
            for (int c = 0; c < 4; c++) acc[nt][c] = 0.f;
        const float* wob = g_Wof + (size_t)w * 64 * 256 + lane * 8;
        uint4 r0[4], r1[4];
        #pragma unroll
        for (int p = 0; p < 4; p++) {
            r0[p] = *(const uint4*)(wob + p * 256);
            r1[p] = *(const uint4*)(wob + p * 256 + 4);
        }
        #pragma unroll 4
        for (int kk = 0; kk < 64; kk++) {
            float4 af = *(const float4*)(qkc + kk * 128 + lane * 4);
            uint4 b0 = r0[kk & 3], b1 = r1[kk & 3];
            if (kk + 4 < 64) {
                r0[kk & 3] = *(const uint4*)(wob + (kk + 4) * 256);
                r1[kk & 3] = *(const uint4*)(wob + (kk + 4) * 256 + 4);
            }
            uint32_t a[4] = {f2u(af.x), f2u(af.y), f2u(af.z), f2u(af.w)};
            uint32_t bu[4][2] = {{b0.x, b0.y}, {b0.z, b0.w}, {b1.x, b1.y}, {b1.z, b1.w}};
            #pragma unroll
            for (int nt = 0; nt < 4; nt++)
                mma_tf32(acc[nt], a, bu[nt]);
        }
        #pragma unroll
        for (int nt = 0; nt < 4; nt++) {
            int c = w * 32 + nt * 8 + 2 * tg;
            float2 bb = *(const float2*)(bo + c);
            *(float2*)(out + ((size_t)(b * 16 + g)) * 512 + c) =
                make_float2(acc[nt][0] + bb.x, acc[nt][1] + bb.y);
            *(float2*)(out + ((size_t)(b * 16 + g + 8)) * 512 + c) =
                make_float2(acc[nt][2] + bb.x, acc[nt][3] + bb.y);
        }
    }
}

// ---------------------------------------------------------------------------
extern "C" void kernel_launch(void* const* d_in, const int* in_sizes, int n_in,
                              void* d_out, int out_size)
{
    const float* x  = (const float*)d_in[0];
    const float* l  = (const float*)d_in[1];
    const float* Wq = (const float*)d_in[2];
    const float* Wk = (const float*)d_in[3];
    const float* Wv = (const float*)d_in[4];
    const float* Wo = (const float*)d_in[5];
    const float* bo = (const float*)d_in[6];
    float* out = (float*)d_out;

    const int smem_f = F7_TOT * 4;           // 200704
    cudaFuncSetAttribute(fattn7, cudaFuncAttributeMaxDynamicSharedMemorySize, smem_f);

    prep_w<<<2048, 256>>>(Wq, Wk, Wv, Wo);
    fattn7<<<1024, 512, smem_f>>>(x, l, bo, out);
}

// round 14
// speedup vs baseline: 1.0198x; 1.0198x over previous
#include <cuda_runtime.h>
#include <cstdint>
#include <cstddef>

// ---------------------------------------------------------------------------
// CrossAttentionDecoder: B=1024 (8*128), n_tok=16, num_latents=128, d=512,
// heads=8, dh=64.  Mask: batch b attends only to latents j <= (b % 128).
//
// Fully-fused, one CTA per batch b (512 threads), superchunked d-loop.
// R14: R12 structure + quad-contiguous weight fragments (2x LDG.128 per
// k-step, distance-1 prefetch, no rings) + pass-2 order {3,0,1,2} reusing
// the lc tile staged by pass 1's last superchunk.
// ---------------------------------------------------------------------------

#define DIMK 512

// layouts: g_Wqf/g_Wvf/g_Wof: [n4 16][kk 64][lane 32][nt 4][2]
//          g_Wkf:             [h 8][ntg4 16][ks 8][lane 32][nt 4][2]
__device__ float g_Wqf[16 * 64 * 32 * 8];
__device__ float g_Wvf[16 * 64 * 32 * 8];
__device__ float g_Wof[16 * 64 * 32 * 8];
__device__ float g_Wkf[8 * 16 * 8 * 32 * 8];

// ---------------- helpers ---------------------------------------------------
__device__ __forceinline__ float to_tf32(float x) {
    uint32_t u; asm("cvt.rna.tf32.f32 %0, %1;" : "=r"(u) : "f"(x));
    return __uint_as_float(u);
}
__device__ __forceinline__ uint32_t f2u(float x) { return __float_as_uint(x); }

__device__ __forceinline__ void mma_tf32(float* d, const uint32_t* a, const uint32_t* b) {
    asm volatile(
        "mma.sync.aligned.m16n8k8.row.col.f32.tf32.tf32.f32 "
        "{%0,%1,%2,%3}, {%4,%5,%6,%7}, {%8,%9}, {%0,%1,%2,%3};\n"
        : "+f"(d[0]), "+f"(d[1]), "+f"(d[2]), "+f"(d[3])
        : "r"(a[0]), "r"(a[1]), "r"(a[2]), "r"(a[3]),
          "r"(b[0]), "r"(b[1]));
}

// ---------------------------------------------------------------------------
// prep_w: fragment-pack Wq, Wv, Wo and Wk (transposed) into lane-contiguous
// nt-quad layout (verified in R13).
// ---------------------------------------------------------------------------
__global__ __launch_bounds__(256)
void prep_w(const float* __restrict__ Wq, const float* __restrict__ Wk,
            const float* __restrict__ Wv, const float* __restrict__ Wo)
{
    int gid = blockIdx.x * 256 + threadIdx.x;        // 2048 blocks
    int lane = gid & 31, kk = (gid >> 5) & 63, nv = gid >> 11;   // nv 0..255
    int g = lane >> 2, tg = lane & 3;
    if (nv < 192) {
        const float* W; float* dst; int dn;
        if (nv < 64)       { W = Wq; dst = g_Wqf; dn = nv; }
        else if (nv < 128) { W = Wv; dst = g_Wvf; dn = nv - 64; }
        else               { W = Wo; dst = g_Wof; dn = nv - 128; }
        float v0 = to_tf32(W[(size_t)(dn * 8 + g) * DIMK + kk * 8 + tg]);
        float v1 = to_tf32(W[(size_t)(dn * 8 + g) * DIMK + kk * 8 + tg + 4]);
        *(float2*)(dst + (size_t)((((dn >> 2) * 64 + kk) * 32 + lane) * 4 + (dn & 3)) * 2) =
            make_float2(v0, v1);
    } else {
        int t = nv - 192;            // 0..63
        int h = t >> 3, ks = t & 7;
        int ntg = kk;
        float v0 = to_tf32(Wk[(size_t)(h * 64 + ks * 8 + tg) * DIMK + ntg * 8 + g]);
        float v1 = to_tf32(Wk[(size_t)(h * 64 + ks * 8 + tg + 4) * DIMK + ntg * 8 + g]);
        *(float2*)(g_Wkf + (size_t)(((((h * 16 + (ntg >> 2)) * 8 + ks) * 32 + lane) * 4 +
                                     (ntg & 3)) * 2)) = make_float2(v0, v1);
    }
}

// ---------------------------------------------------------------------------
// fattn8: one CTA per batch b (heavy-first order), 512 threads (16 warps).
// Smem (floats): R 16384 (qf pass1 / Pf after) | qkc 16384 | lc 17408
// ---------------------------------------------------------------------------
#define F8_R   0
#define F8_QKC 16384
#define F8_LC  32768
#define F8_TOT 50176

__global__ __launch_bounds__(512, 1)
void fattn8(const float* __restrict__ x, const float* __restrict__ l,
            const float* __restrict__ bo, float* __restrict__ out)
{
    extern __shared__ __align__(16) float sm[];
    float* qf  = sm + F8_R;      // pass1: q a-frags [8h][8ks][128]
    float* Pf  = sm + F8_R;      // post-pass1: P a-frags [8mt][16ksj][128]
    float* qkc = sm + F8_QKC;    // qk/pl a-frags [8mt][16ksd][128]; also x/ov frags
    float* lc  = sm + F8_LC;     // l tiles [jt16][dtile16] x 68

    const int bid = blockIdx.x;
    const int b = (bid & 7) * 128 + (127 - (bid >> 3));   // heavy-first
    const int nj = (b & 127) + 1;
    const int T = (nj + 7) >> 3;
    const int njc8 = T << 3;

    const int tid = threadIdx.x, w = tid >> 5, lane = tid & 31;
    const int g = lane >> 2, tg = lane & 3;
    const int wm = w >> 2, wn = w & 3;        // scores mapping
    const int amt = w >> 1, anh = w & 1;      // phase A / pass2 / ov mapping

    // conflict-free lc tile read offsets (R8-verified)
    const int p1o0 = g * 4 + tg;
    const int p1o1 = ((g ^ 4) + 8) * 4 + tg;
    const int h2 = g >> 2, gl = g & 3;
    const int p2o0 = ((tg ^ (h2 << 2)) + (h2 << 3)) * 4 + gl;
    const int p2o1 = (((tg + 4) ^ (h2 << 2)) + (h2 << 3)) * 4 + gl;

    // ============ prologue: stage x a-frags into qkc ============
    #pragma unroll
    for (int it = 0; it < 4; it++) {
        int idx = tid + it * 512;           // 0..2047
        int i = idx >> 7, c4 = (idx & 127) * 4;
        float4 v = *(const float4*)(x + ((size_t)(b * 16 + i)) * 512 + c4);
        float vv[4] = {v.x, v.y, v.z, v.w};
        #pragma unroll
        for (int e = 0; e < 4; e++) {
            int c = c4 + e;
            qkc[(c >> 3) * 128 + ((i & 7) * 4 + (c & 3)) * 4 +
                ((i >> 3) + 2 * ((c >> 2) & 1))] = to_tf32(vv[e]);
        }
    }
    __syncthreads();

    // ============ Q-proj: q = x @ Wq^T -> qf (distance-1 prefetch) ============
    {
        float acc[4][4];
        #pragma unroll
        for (int nt = 0; nt < 4; nt++)
            #pragma unroll
            for (int c = 0; c < 4; c++) acc[nt][c] = 0.f;
        const float* wqb = g_Wqf + (size_t)w * 64 * 256 + lane * 8;
        uint4 b0p = *(const uint4*)(wqb);
        uint4 b1p = *(const uint4*)(wqb + 4);
        for (int kk = 0; kk < 64; kk++) {
            float4 af = *(const float4*)(qkc + kk * 128 + lane * 4);
            uint4 b0 = b0p, b1 = b1p;
            if (kk < 63) {
                b0p = *(const uint4*)(wqb + (kk + 1) * 256);
                b1p = *(const uint4*)(wqb + (kk + 1) * 256 + 4);
            }
            uint32_t a[4] = {f2u(af.x), f2u(af.y), f2u(af.z), f2u(af.w)};
            uint32_t bu[4][2] = {{b0.x, b0.y}, {b0.z, b0.w}, {b1.x, b1.y}, {b1.z, b1.w}};
            #pragma unroll
            for (int nt = 0; nt < 4; nt++)
                mma_tf32(acc[nt], a, bu[nt]);
        }
        __syncthreads();   // qkc (x-frags) dead after all warps' reads
        #pragma unroll
        for (int nt = 0; nt < 4; nt++) {
            int c0 = w * 32 + nt * 8 + 2 * tg;
            #pragma unroll
            for (int e = 0; e < 4; e++) {
                int r = g + ((e >> 1) << 3);
                int c = c0 + (e & 1);
                int h = c >> 6, ks = (c & 63) >> 3;
                qf[(h * 8 + ks) * 128 + (g * 4 + (c & 3)) * 4 +
                   ((r >> 3) + 2 * ((c >> 2) & 1))] = to_tf32(acc[nt][e]);
            }
        }
    }
    __syncthreads();

    float sacc[2][4][4];
    #pragma unroll
    for (int i = 0; i < 2; i++)
        #pragma unroll
        for (int j = 0; j < 4; j++)
            #pragma unroll
            for (int c = 0; c < 4; c++) sacc[i][j][c] = 0.f;

    // ================= pass 1: scores, 4 superchunks of 128 d =================
    for (int ch2 = 0; ch2 < 4; ch2++) {
        #pragma unroll
        for (int sub = 0; sub < 2; sub++) {
            const int d0 = ch2 * 128 + sub * 64;
            // l loads first; phase A overlaps the latency
            float4 sv[4];
            #pragma unroll
            for (int it = 0; it < 4; it++) {
                int i4 = tid + it * 512;
                int j = i4 >> 4, dq = i4 & 15;
                sv[it] = make_float4(0.f, 0.f, 0.f, 0.f);
                if (j < nj)
                    sv[it] = *(const float4*)(l + ((size_t)(b * 128 + j)) * 512 + d0 + dq * 4);
            }
            // phase A: qk d-cols [d0, d0+64) for head amt (distance-1 prefetch)
            float aacc[4][4];
            #pragma unroll
            for (int nt = 0; nt < 4; nt++)
                #pragma unroll
                for (int c = 0; c < 4; c++) aacc[nt][c] = 0.f;
            {
                const float* wkb = g_Wkf +
                    (size_t)((amt * 16 + ch2 * 4 + sub * 2 + anh) * 8) * 256 + lane * 8;
                uint4 b0p = *(const uint4*)(wkb);
                uint4 b1p = *(const uint4*)(wkb + 4);
                #pragma unroll
                for (int ks = 0; ks < 8; ks++) {
                    float4 ac = *(const float4*)(qf + (amt * 8 + ks) * 128 + lane * 4);
                    uint4 b0 = b0p, b1 = b1p;
                    if (ks < 7) {
                        b0p = *(const uint4*)(wkb + (ks + 1) * 256);
                        b1p = *(const uint4*)(wkb + (ks + 1) * 256 + 4);
                    }
                    uint32_t a[4] = {f2u(ac.x), f2u(ac.y), f2u(ac.z), f2u(ac.w)};
                    uint32_t bu[4][2] = {{b0.x, b0.y}, {b0.z, b0.w}, {b1.x, b1.y}, {b1.z, b1.w}};
                    #pragma unroll
                    for (int nt = 0; nt < 4; nt++)
                        mma_tf32(aacc[nt], a, bu[nt]);
                }
            }
            // scatter qk-half into qkc a-frags (superchunk ksd = sub*8 + ..)
            #pragma unroll
            for (int nt = 0; nt < 4; nt++) {
                int c0 = anh * 32 + nt * 8 + 2 * tg;
                #pragma unroll
                for (int e = 0; e < 4; e++) {
                    int c = c0 + (e & 1);
                    qkc[((amt * 16 + sub * 8 + (c >> 3)) * 32 + g * 4 + (c & 3)) * 4 +
                        ((e >> 1) + 2 * ((c >> 2) & 1))] = to_tf32(aacc[nt][e]);
                }
            }
            // lc STS (tiles [jt][sub*8 + dtile])
            #pragma unroll
            for (int it = 0; it < 4; it++) {
                int i4 = tid + it * 512;
                int j = i4 >> 4, dq = i4 & 15;
                if (j < njc8) {
                    int hh = dq & 1;
                    int X = ((j & 7) ^ (hh << 2)) + (hh << 3);
                    float4 o;
                    o.x = to_tf32(sv[it].x); o.y = to_tf32(sv[it].y);
                    o.z = to_tf32(sv[it].z); o.w = to_tf32(sv[it].w);
                    *(float4*)(lc + ((j >> 3) * 16 + sub * 8 + (dq >> 1)) * 68 + X * 4) = o;
                }
            }
        }
        __syncthreads();

        // scores mma over 16 d-tiles
        #pragma unroll
        for (int ksd = 0; ksd < 16; ksd++) {
            float4 af0 = *(const float4*)(qkc + ((wm * 2 + 0) * 16 + ksd) * 128 + lane * 4);
            float4 af1 = *(const float4*)(qkc + ((wm * 2 + 1) * 16 + ksd) * 128 + lane * 4);
            uint32_t a0[4] = {f2u(af0.x), f2u(af0.y), f2u(af0.z), f2u(af0.w)};
            uint32_t a1[4] = {f2u(af1.x), f2u(af1.y), f2u(af1.z), f2u(af1.w)};
            #pragma unroll
            for (int jt4 = 0; jt4 < 4; jt4++) {
                int jt = wn + jt4 * 4;
                if (jt < T) {
                    int tb = (jt * 16 + ksd) * 68;
                    uint32_t bu[2] = { f2u(lc[tb + p1o0]), f2u(lc[tb + p1o1]) };
                    mma_tf32(sacc[0][jt4], a0, bu);
                    mma_tf32(sacc[1][jt4], a1, bu);
                }
            }
        }
        if (ch2 < 3) __syncthreads();    // after ch2=3, lc is preserved for pass 2
    }
    __syncthreads();

    // ---- scatter scores -> Pf (a-frag layout, scaled); Pf overlays dead qf ----
    #pragma unroll
    for (int mt = 0; mt < 2; mt++) {
        #pragma unroll
        for (int jt4 = 0; jt4 < 4; jt4++) {
            int jt = wn + jt4 * 4;
            if (jt < T) {
                #pragma unroll
                for (int e = 0; e < 4; e++) {
                    int j = jt * 8 + 2 * tg + (e & 1);
                    Pf[((wm * 2 + mt) * 16 + jt) * 128 + (g * 4 + (j & 3)) * 4 +
                       ((e >> 1) + 2 * ((j >> 2) & 1))] = sacc[mt][jt4][e] * 0.125f;
                }
            }
        }
    }
    __syncthreads();

    // ---- softmax: warp w owns rows w*8 .. w*8+7 (packed-frag addressing) ----
    #pragma unroll
    for (int rr = 0; rr < 8; rr++) {
        int row = w * 8 + rr;
        int mt = row >> 4, rl = row & 15;
        int base = mt * 16 * 128 + ((rl & 7) * 4) * 4 + (rl >> 3);
        float mx = -1e30f;
        for (int j = lane; j < nj; j += 32)
            mx = fmaxf(mx, Pf[base + (j >> 3) * 128 + (j & 3) * 4 + 2 * ((j >> 2) & 1)]);
        #pragma unroll
        for (int o = 16; o; o >>= 1) mx = fmaxf(mx, __shfl_xor_sync(0xffffffffu, mx, o));
        float e4[4]; int cnt = 0; float s = 0.f;
        for (int j = lane; j < nj; j += 32) {
            float ev = __expf(Pf[base + (j >> 3) * 128 + (j & 3) * 4 + 2 * ((j >> 2) & 1)] - mx);
            e4[cnt++] = ev; s += ev;
        }
        #pragma unroll
        for (int o = 16; o; o >>= 1) s += __shfl_xor_sync(0xffffffffu, s, o);
        float inv = 1.f / s;
        cnt = 0;
        for (int j = lane; j < njc8; j += 32) {
            float val = (j < nj) ? e4[cnt++] * inv : 0.f;
            Pf[base + (j >> 3) * 128 + (j & 3) * 4 + 2 * ((j >> 2) & 1)] = to_tf32(val);
        }
    }
    __syncthreads();   // Pf visible to all warps; lc still holds superchunk 3

    // ================= pass 2: pl + ov, order {3,0,1,2} (lc reuse) =================
    float ovacc[4][4];
    #pragma unroll
    for (int nt = 0; nt < 4; nt++)
        #pragma unroll
        for (int c = 0; c < 4; c++) ovacc[nt][c] = 0.f;

    const int order[4] = {3, 0, 1, 2};
    for (int it2 = 0; it2 < 4; it2++) {
        const int ch2 = order[it2];
        if (it2 > 0) {
            const int prev = order[it2 - 1];
            #pragma unroll
            for (int sub = 0; sub < 2; sub++) {
                const int d0 = ch2 * 128 + sub * 64;
                float4 sv[4];
                #pragma unroll
                for (int it = 0; it < 4; it++) {
                    int i4 = tid + it * 512;
                    int j = i4 >> 4, dq = i4 & 15;
                    sv[it] = make_float4(0.f, 0.f, 0.f, 0.f);
                    if (j < nj)
                        sv[it] = *(const float4*)(l + ((size_t)(b * 128 + j)) * 512 + d0 + dq * 4);
                }
                // ov for previous chunk, half 'sub' (overlaps loads)
                {
                    const int kkb = prev * 16 + sub * 8;
                    const float* wvb = g_Wvf +
                        ((size_t)(amt * 2 + anh) * 64 + kkb) * 256 + lane * 8;
                    uint4 b0p = *(const uint4*)(wvb);
                    uint4 b1p = *(const uint4*)(wvb + 4);
                    #pragma unroll
                    for (int ksd = 0; ksd < 8; ksd++) {
                        float4 af = *(const float4*)(qkc +
                            ((amt * 16 + sub * 8 + ksd)) * 128 + lane * 4);
                        uint4 b0 = b0p, b1 = b1p;
                        if (ksd < 7) {
                            b0p = *(const uint4*)(wvb + (ksd + 1) * 256);
                            b1p = *(const uint4*)(wvb + (ksd + 1) * 256 + 4);
                        }
                        uint32_t a[4] = {f2u(af.x), f2u(af.y), f2u(af.z), f2u(af.w)};
                        uint32_t bu[4][2] = {{b0.x, b0.y}, {b0.z, b0.w},
                                             {b1.x, b1.y}, {b1.z, b1.w}};
                        #pragma unroll
                        for (int nt = 0; nt < 4; nt++)
                            mma_tf32(ovacc[nt], a, bu[nt]);
                    }
                }
                // lc STS
                #pragma unroll
                for (int it = 0; it < 4; it++) {
                    int i4 = tid + it * 512;
                    int j = i4 >> 4, dq = i4 & 15;
                    if (j < njc8) {
                        int hh = dq & 1;
                        int X = ((j & 7) ^ (hh << 2)) + (hh << 3);
                        float4 o;
                        o.x = to_tf32(sv[it].x); o.y = to_tf32(sv[it].y);
                        o.z = to_tf32(sv[it].z); o.w = to_tf32(sv[it].w);
                        *(float4*)(lc + ((j >> 3) * 16 + sub * 8 + (dq >> 1)) * 68 + X * 4) = o;
                    }
                }
            }
            __syncthreads();
        }

        // pl over both halves -> qkc
        #pragma unroll
        for (int sub = 0; sub < 2; sub++) {
            float placc[4][4];
            #pragma unroll
            for (int nt = 0; nt < 4; nt++)
                #pragma unroll
                for (int c = 0; c < 4; c++) placc[nt][c] = 0.f;
            for (int ksj = 0; ksj < T; ksj++) {
                float4 af = *(const float4*)(Pf + (amt * 16 + ksj) * 128 + lane * 4);
                uint32_t a[4] = {f2u(af.x), f2u(af.y), f2u(af.z), f2u(af.w)};
                #pragma unroll
                for (int nt = 0; nt < 4; nt++) {
                    int tb = (ksj * 16 + sub * 8 + anh * 4 + nt) * 68;
                    uint32_t bu[2] = { f2u(lc[tb + p2o0]), f2u(lc[tb + p2o1]) };
                    mma_tf32(placc[nt], a, bu);
                }
            }
            #pragma unroll
            for (int nt = 0; nt < 4; nt++) {
                int c0 = anh * 32 + nt * 8 + 2 * tg;
                #pragma unroll
                for (int e = 0; e < 4; e++) {
                    int c = c0 + (e & 1);
                    qkc[((amt * 16 + sub * 8 + (c >> 3)) * 32 + g * 4 + (c & 3)) * 4 +
                        ((e >> 1) + 2 * ((c >> 2) & 1))] = to_tf32(placc[nt][e]);
                }
            }
        }
        __syncthreads();
    }

    // ---- final ov (chunk order[3] = 2, both halves) ----
    #pragma unroll
    for (int sub = 0; sub < 2; sub++) {
        const int kkb = 2 * 16 + sub * 8;
        const float* wvb = g_Wvf + ((size_t)(amt * 2 + anh) * 64 + kkb) * 256 + lane * 8;
        uint4 b0p = *(const uint4*)(wvb);
        uint4 b1p = *(const uint4*)(wvb + 4);
        #pragma unroll
        for (int ksd = 0; ksd < 8; ksd++) {
            float4 af = *(const float4*)(qkc + ((amt * 16 + sub * 8 + ksd)) * 128 + lane * 4);
            uint4 b0 = b0p, b1 = b1p;
            if (ksd < 7) {
                b0p = *(const uint4*)(wvb + (ksd + 1) * 256);
                b1p = *(const uint4*)(wvb + (ksd + 1) * 256 + 4);
            }
            uint32_t a[4] = {f2u(af.x), f2u(af.y), f2u(af.z), f2u(af.w)};
            uint32_t bu[4][2] = {{b0.x, b0.y}, {b0.z, b0.w}, {b1.x, b1.y}, {b1.z, b1.w}};
            #pragma unroll
            for (int nt = 0; nt < 4; nt++)
                mma_tf32(ovacc[nt], a, bu[nt]);
        }
    }
    __syncthreads();   // all ov reads of qkc complete

    // ============ epilogue: ov -> a-frags, out = ov @ Wo^T + bo ============
    #pragma unroll
    for (int nt = 0; nt < 4; nt++) {
        int c0 = amt * 64 + anh * 32 + nt * 8 + 2 * tg;
        #pragma unroll
        for (int e = 0; e < 4; e++) {
            int r = g + ((e >> 1) << 3);          // token i
            int c = c0 + (e & 1);
            qkc[(c >> 3) * 128 + (g * 4 + (c & 3)) * 4 +
                ((r >> 3) + 2 * ((c >> 2) & 1))] = to_tf32(ovacc[nt][e]);
        }
    }
    __syncthreads();

    // O-proj (distance-1 prefetch)
    {
        float acc[4][4];
        #pragma unroll
        for (int nt = 0; nt < 4; nt++)
            #pragma unroll
            for (int c = 0; c < 4; c++) acc[nt][c] = 0.f;
        const float* wob = g_Wof + (size_t)w * 64 * 256 + lane * 8;
        uint4 b0p = *(const uint4*)(wob);
        uint4 b1p = *(const uint4*)(wob + 4);
        for (int kk = 0; kk < 64; kk++) {
            float4 af = *(const float4*)(qkc + kk * 128 + lane * 4);
            uint4 b0 = b0p, b1 = b1p;
            if (kk < 63) {
                b0p = *(const uint4*)(wob + (kk + 1) * 256);
                b1p = *(const uint4*)(wob + (kk + 1) * 256 + 4);
            }
            uint32_t a[4] = {f2u(af.x), f2u(af.y), f2u(af.z), f2u(af.w)};
            uint32_t bu[4][2] = {{b0.x, b0.y}, {b0.z, b0.w}, {b1.x, b1.y}, {b1.z, b1.w}};
            #pragma unroll
            for (int nt = 0; nt < 4; nt++)
                mma_tf32(acc[nt], a, bu[nt]);
        }
        #pragma unroll
        for (int nt = 0; nt < 4; nt++) {
            int c = w * 32 + nt * 8 + 2 * tg;
            float2 bb = *(const float2*)(bo + c);
            *(float2*)(out + ((size_t)(b * 16 + g)) * 512 + c) =
                make_float2(acc[nt][0] + bb.x, acc[nt][1] + bb.y);
            *(float2*)(out + ((size_t)(b * 16 + g + 8)) * 512 + c) =
                make_float2(acc[nt][2] + bb.x, acc[nt][3] + bb.y);
        }
    }
}

// ---------------------------------------------------------------------------
extern "C" void kernel_launch(void* const* d_in, const int* in_sizes, int n_in,
                              void* d_out, int out_size)
{
    const float* x  = (const float*)d_in[0];
    const float* l  = (const float*)d_in[1];
    const float* Wq = (const float*)d_in[2];
    const float* Wk = (const float*)d_in[3];
    const float* Wv = (const float*)d_in[4];
    const float* Wo = (const float*)d_in[5];
    const float* bo = (const float*)d_in[6];
    float* out = (float*)d_out;

    const int smem_f = F8_TOT * 4;           // 200704
    cudaFuncSetAttribute(fattn8, cudaFuncAttributeMaxDynamicSharedMemorySize, smem_f);

    prep_w<<<2048, 256>>>(Wq, Wk, Wv, Wo);
    fattn8<<<1024, 512, smem_f>>>(x, l, bo, out);
}

// round 15
// speedup vs baseline: 1.1077x; 1.0861x over previous
#include <cuda_runtime.h>
#include <cstdint>
#include <cstddef>

// ---------------------------------------------------------------------------
// CrossAttentionDecoder: B=1024 (8*128), n_tok=16, num_latents=128, d=512,
// heads=8, dh=64.  Mask: batch b attends only to latents j <= (b % 128).
//
// Fully-fused, one CTA per batch b (512 threads), superchunked d-loop
// (R12 structure, uint2 weight fragments, distance-1 prefetch).
// R15: pass-2 superchunk order {3,0,1,2} reuses the lc tile staged by
// pass 1's last superchunk — one full staging round deleted.
// ---------------------------------------------------------------------------

#define DIMK 512

__device__ float g_Wqf[64 * 64 * 32 * 2];
__device__ float g_Wvf[64 * 64 * 32 * 2];
__device__ float g_Wof[64 * 64 * 32 * 2];
__device__ float g_Wkf[8 * 64 * 8 * 32 * 2];        // transposed pack for qk

// ---------------- helpers ---------------------------------------------------
__device__ __forceinline__ float to_tf32(float x) {
    uint32_t u; asm("cvt.rna.tf32.f32 %0, %1;" : "=r"(u) : "f"(x));
    return __uint_as_float(u);
}
__device__ __forceinline__ uint32_t f2u(float x) { return __float_as_uint(x); }

__device__ __forceinline__ void mma_tf32(float* d, const uint32_t* a, const uint32_t* b) {
    asm volatile(
        "mma.sync.aligned.m16n8k8.row.col.f32.tf32.tf32.f32 "
        "{%0,%1,%2,%3}, {%4,%5,%6,%7}, {%8,%9}, {%0,%1,%2,%3};\n"
        : "+f"(d[0]), "+f"(d[1]), "+f"(d[2]), "+f"(d[3])
        : "r"(a[0]), "r"(a[1]), "r"(a[2]), "r"(a[3]),
          "r"(b[0]), "r"(b[1]));
}

// ---------------------------------------------------------------------------
// prep_w: fragment-pack Wq, Wv, Wo (B[n][k] = W[n][k]) and Wk transposed.
// ---------------------------------------------------------------------------
__global__ __launch_bounds__(256)
void prep_w(const float* __restrict__ Wq, const float* __restrict__ Wk,
            const float* __restrict__ Wv, const float* __restrict__ Wo)
{
    int gid = blockIdx.x * 256 + threadIdx.x;        // 2048 blocks
    int lane = gid & 31, kk = (gid >> 5) & 63, nv = gid >> 11;   // nv 0..255
    int g = lane >> 2, tg = lane & 3;
    if (nv < 192) {
        const float* W; float* dst; int dn;
        if (nv < 64)       { W = Wq; dst = g_Wqf; dn = nv; }
        else if (nv < 128) { W = Wv; dst = g_Wvf; dn = nv - 64; }
        else               { W = Wo; dst = g_Wof; dn = nv - 128; }
        float v0 = to_tf32(W[(size_t)(dn * 8 + g) * DIMK + kk * 8 + tg]);
        float v1 = to_tf32(W[(size_t)(dn * 8 + g) * DIMK + kk * 8 + tg + 4]);
        *(float2*)(dst + ((size_t)(dn * 64 + kk) * 32 + lane) * 2) = make_float2(v0, v1);
    } else {
        int t = nv - 192;            // 0..63
        int h = t >> 3, ks = t & 7;
        int ntg = kk;
        float v0 = to_tf32(Wk[(size_t)(h * 64 + ks * 8 + tg) * DIMK + ntg * 8 + g]);
        float v1 = to_tf32(Wk[(size_t)(h * 64 + ks * 8 + tg + 4) * DIMK + ntg * 8 + g]);
        *(float2*)(g_Wkf + ((size_t)((h * 64 + ntg) * 8 + ks) * 32 + lane) * 2) =
            make_float2(v0, v1);
    }
}

// ---------------------------------------------------------------------------
// fattn9: one CTA per batch b (heavy-first order), 512 threads (16 warps).
// Smem (floats): R 16384 (qf pass1 / Pf after) | qkc 16384 | lc 17408
// ---------------------------------------------------------------------------
#define F9_R   0
#define F9_QKC 16384
#define F9_LC  32768
#define F9_TOT 50176

__global__ __launch_bounds__(512, 1)
void fattn9(const float* __restrict__ x, const float* __restrict__ l,
            const float* __restrict__ bo, float* __restrict__ out)
{
    extern __shared__ __align__(16) float sm[];
    float* qf  = sm + F9_R;      // pass1: q a-frags [8h][8ks][128]
    float* Pf  = sm + F9_R;      // post-pass1: P a-frags [8mt][16ksj][128]
    float* qkc = sm + F9_QKC;    // qk/pl a-frags [8mt][16ksd][128]; also x/ov frags
    float* lc  = sm + F9_LC;     // l tiles [jt16][dtile16] x 68

    const int bid = blockIdx.x;
    const int b = (bid & 7) * 128 + (127 - (bid >> 3));   // heavy-first
    const int nj = (b & 127) + 1;
    const int T = (nj + 7) >> 3;
    const int njc8 = T << 3;

    const int tid = threadIdx.x, w = tid >> 5, lane = tid & 31;
    const int g = lane >> 2, tg = lane & 3;
    const int wm = w >> 2, wn = w & 3;        // scores mapping
    const int amt = w >> 1, anh = w & 1;      // phase A / pass2 / ov mapping

    // conflict-free lc tile read offsets (R8-verified)
    const int p1o0 = g * 4 + tg;
    const int p1o1 = ((g ^ 4) + 8) * 4 + tg;
    const int h2 = g >> 2, gl = g & 3;
    const int p2o0 = ((tg ^ (h2 << 2)) + (h2 << 3)) * 4 + gl;
    const int p2o1 = (((tg + 4) ^ (h2 << 2)) + (h2 << 3)) * 4 + gl;

    // ============ prologue: stage x a-frags into qkc ============
    #pragma unroll
    for (int it = 0; it < 4; it++) {
        int idx = tid + it * 512;           // 0..2047
        int i = idx >> 7, c4 = (idx & 127) * 4;
        float4 v = *(const float4*)(x + ((size_t)(b * 16 + i)) * 512 + c4);
        float vv[4] = {v.x, v.y, v.z, v.w};
        #pragma unroll
        for (int e = 0; e < 4; e++) {
            int c = c4 + e;
            qkc[(c >> 3) * 128 + ((i & 7) * 4 + (c & 3)) * 4 +
                ((i >> 3) + 2 * ((c >> 2) & 1))] = to_tf32(vv[e]);
        }
    }
    __syncthreads();

    // ============ Q-proj: q = x @ Wq^T -> qf (per-head a-frags) ============
    {
        float acc[4][4];
        #pragma unroll
        for (int nt = 0; nt < 4; nt++)
            #pragma unroll
            for (int c = 0; c < 4; c++) acc[nt][c] = 0.f;
        const float* wqb = g_Wqf + ((size_t)(w * 4) * 64) * 64 + lane * 2;
        uint2 bp[4];
        #pragma unroll
        for (int nt = 0; nt < 4; nt++) bp[nt] = *(const uint2*)(wqb + nt * 4096);
        for (int kk = 0; kk < 64; kk++) {
            float4 af = *(const float4*)(qkc + kk * 128 + lane * 4);
            uint32_t a[4] = {f2u(af.x), f2u(af.y), f2u(af.z), f2u(af.w)};
            uint2 bc[4];
            #pragma unroll
            for (int nt = 0; nt < 4; nt++) bc[nt] = bp[nt];
            if (kk < 63) {
                #pragma unroll
                for (int nt = 0; nt < 4; nt++)
                    bp[nt] = *(const uint2*)(wqb + nt * 4096 + (kk + 1) * 64);
            }
            #pragma unroll
            for (int nt = 0; nt < 4; nt++)
                mma_tf32(acc[nt], a, (const uint32_t*)&bc[nt]);
        }
        __syncthreads();   // qkc (x-frags) dead after all warps' reads
        #pragma unroll
        for (int nt = 0; nt < 4; nt++) {
            int c0 = w * 32 + nt * 8 + 2 * tg;
            #pragma unroll
            for (int e = 0; e < 4; e++) {
                int r = g + ((e >> 1) << 3);
                int c = c0 + (e & 1);
                int h = c >> 6, ks = (c & 63) >> 3;
                qf[(h * 8 + ks) * 128 + (g * 4 + (c & 3)) * 4 +
                   ((r >> 3) + 2 * ((c >> 2) & 1))] = to_tf32(acc[nt][e]);
            }
        }
    }
    __syncthreads();

    float sacc[2][4][4];
    #pragma unroll
    for (int i = 0; i < 2; i++)
        #pragma unroll
        for (int j = 0; j < 4; j++)
            #pragma unroll
            for (int c = 0; c < 4; c++) sacc[i][j][c] = 0.f;

    // ================= pass 1: scores, 4 superchunks of 128 d =================
    for (int ch2 = 0; ch2 < 4; ch2++) {
        #pragma unroll
        for (int sub = 0; sub < 2; sub++) {
            const int d0 = ch2 * 128 + sub * 64;
            // l loads first; phase A overlaps the latency
            float4 sv[4];
            #pragma unroll
            for (int it = 0; it < 4; it++) {
                int i4 = tid + it * 512;
                int j = i4 >> 4, dq = i4 & 15;
                sv[it] = make_float4(0.f, 0.f, 0.f, 0.f);
                if (j < nj)
                    sv[it] = *(const float4*)(l + ((size_t)(b * 128 + j)) * 512 + d0 + dq * 4);
            }
            // phase A: qk d-cols [d0, d0+64) for head amt
            float aacc[4][4];
            #pragma unroll
            for (int nt = 0; nt < 4; nt++)
                #pragma unroll
                for (int c = 0; c < 4; c++) aacc[nt][c] = 0.f;
            {
                const float* wkb = g_Wkf +
                    ((size_t)(amt * 64 + ch2 * 16 + sub * 8 + anh * 4)) * 512 + lane * 2;
                uint2 bp[4];
                #pragma unroll
                for (int nt = 0; nt < 4; nt++) bp[nt] = *(const uint2*)(wkb + nt * 512);
                #pragma unroll
                for (int ks = 0; ks < 8; ks++) {
                    float4 ac = *(const float4*)(qf + (amt * 8 + ks) * 128 + lane * 4);
                    uint2 bc[4];
                    #pragma unroll
                    for (int nt = 0; nt < 4; nt++) bc[nt] = bp[nt];
                    if (ks < 7) {
                        #pragma unroll
                        for (int nt = 0; nt < 4; nt++)
                            bp[nt] = *(const uint2*)(wkb + nt * 512 + (ks + 1) * 64);
                    }
                    uint32_t a[4] = {f2u(ac.x), f2u(ac.y), f2u(ac.z), f2u(ac.w)};
                    #pragma unroll
                    for (int nt = 0; nt < 4; nt++)
                        mma_tf32(aacc[nt], a, (const uint32_t*)&bc[nt]);
                }
            }
            // scatter qk-half into qkc a-frags (superchunk ksd = sub*8 + ..)
            #pragma unroll
            for (int nt = 0; nt < 4; nt++) {
                int c0 = anh * 32 + nt * 8 + 2 * tg;
                #pragma unroll
                for (int e = 0; e < 4; e++) {
                    int c = c0 + (e & 1);
                    qkc[((amt * 16 + sub * 8 + (c >> 3)) * 32 + g * 4 + (c & 3)) * 4 +
                        ((e >> 1) + 2 * ((c >> 2) & 1))] = to_tf32(aacc[nt][e]);
                }
            }
            // lc STS (tiles [jt][sub*8 + dtile])
            #pragma unroll
            for (int it = 0; it < 4; it++) {
                int i4 = tid + it * 512;
                int j = i4 >> 4, dq = i4 & 15;
                if (j < njc8) {
                    int hh = dq & 1;
                    int X = ((j & 7) ^ (hh << 2)) + (hh << 3);
                    float4 o;
                    o.x = to_tf32(sv[it].x); o.y = to_tf32(sv[it].y);
                    o.z = to_tf32(sv[it].z); o.w = to_tf32(sv[it].w);
                    *(float4*)(lc + ((j >> 3) * 16 + sub * 8 + (dq >> 1)) * 68 + X * 4) = o;
                }
            }
        }
        __syncthreads();

        // scores mma over 16 d-tiles
        #pragma unroll
        for (int ksd = 0; ksd < 16; ksd++) {
            float4 af0 = *(const float4*)(qkc + ((wm * 2 + 0) * 16 + ksd) * 128 + lane * 4);
            float4 af1 = *(const float4*)(qkc + ((wm * 2 + 1) * 16 + ksd) * 128 + lane * 4);
            uint32_t a0[4] = {f2u(af0.x), f2u(af0.y), f2u(af0.z), f2u(af0.w)};
            uint32_t a1[4] = {f2u(af1.x), f2u(af1.y), f2u(af1.z), f2u(af1.w)};
            #pragma unroll
            for (int jt4 = 0; jt4 < 4; jt4++) {
                int jt = wn + jt4 * 4;
                if (jt < T) {
                    int tb = (jt * 16 + ksd) * 68;
                    uint32_t bu[2] = { f2u(lc[tb + p1o0]), f2u(lc[tb + p1o1]) };
                    mma_tf32(sacc[0][jt4], a0, bu);
                    mma_tf32(sacc[1][jt4], a1, bu);
                }
            }
        }
        __syncthreads();
        // after ch2 == 3 this sync also fences lc, which is preserved for pass 2
    }

    // ---- scatter scores -> Pf (a-frag layout, scaled); Pf overlays dead qf ----
    #pragma unroll
    for (int mt = 0; mt < 2; mt++) {
        #pragma unroll
        for (int jt4 = 0; jt4 < 4; jt4++) {
            int jt = wn + jt4 * 4;
            if (jt < T) {
                #pragma unroll
                for (int e = 0; e < 4; e++) {
                    int j = jt * 8 + 2 * tg + (e & 1);
                    Pf[((wm * 2 + mt) * 16 + jt) * 128 + (g * 4 + (j & 3)) * 4 +
                       ((e >> 1) + 2 * ((j >> 2) & 1))] = sacc[mt][jt4][e] * 0.125f;
                }
            }
        }
    }
    __syncthreads();

    // ---- softmax: warp w owns rows w*8 .. w*8+7 (packed-frag addressing) ----
    #pragma unroll
    for (int rr = 0; rr < 8; rr++) {
        int row = w * 8 + rr;
        int mt = row >> 4, rl = row & 15;
        int base = mt * 16 * 128 + ((rl & 7) * 4) * 4 + (rl >> 3);
        float mx = -1e30f;
        for (int j = lane; j < nj; j += 32)
            mx = fmaxf(mx, Pf[base + (j >> 3) * 128 + (j & 3) * 4 + 2 * ((j >> 2) & 1)]);
        #pragma unroll
        for (int o = 16; o; o >>= 1) mx = fmaxf(mx, __shfl_xor_sync(0xffffffffu, mx, o));
        float e4[4]; int cnt = 0; float s = 0.f;
        for (int j = lane; j < nj; j += 32) {
            float ev = __expf(Pf[base + (j >> 3) * 128 + (j & 3) * 4 + 2 * ((j >> 2) & 1)] - mx);
            e4[cnt++] = ev; s += ev;
        }
        #pragma unroll
        for (int o = 16; o; o >>= 1) s += __shfl_xor_sync(0xffffffffu, s, o);
        float inv = 1.f / s;
        cnt = 0;
        for (int j = lane; j < njc8; j += 32) {
            float val = (j < nj) ? e4[cnt++] * inv : 0.f;
            Pf[base + (j >> 3) * 128 + (j & 3) * 4 + 2 * ((j >> 2) & 1)] = to_tf32(val);
        }
    }
    __syncthreads();   // Pf visible to all warps; lc still holds superchunk 3

    // ================= pass 2: pl + ov, order {3,0,1,2} (lc reuse) =================
    float ovacc[4][4];
    #pragma unroll
    for (int nt = 0; nt < 4; nt++)
        #pragma unroll
        for (int c = 0; c < 4; c++) ovacc[nt][c] = 0.f;

    const int order[4] = {3, 0, 1, 2};
    for (int it2 = 0; it2 < 4; it2++) {
        const int ch2 = order[it2];
        if (it2 > 0) {
            const int prev = order[it2 - 1];
            #pragma unroll
            for (int sub = 0; sub < 2; sub++) {
                const int d0 = ch2 * 128 + sub * 64;
                float4 sv[4];
                #pragma unroll
                for (int it = 0; it < 4; it++) {
                    int i4 = tid + it * 512;
                    int j = i4 >> 4, dq = i4 & 15;
                    sv[it] = make_float4(0.f, 0.f, 0.f, 0.f);
                    if (j < nj)
                        sv[it] = *(const float4*)(l + ((size_t)(b * 128 + j)) * 512 + d0 + dq * 4);
                }
                // ov for previous chunk, half 'sub' (overlaps loads)
                {
                    const int kkb = prev * 16 + sub * 8;
                    const float* wvb = g_Wvf + (size_t)(amt * 8 + anh * 4) * 4096 +
                                       kkb * 64 + lane * 2;
                    uint2 bp[4];
                    #pragma unroll
                    for (int nt = 0; nt < 4; nt++) bp[nt] = *(const uint2*)(wvb + nt * 4096);
                    #pragma unroll
                    for (int ksd = 0; ksd < 8; ksd++) {
                        float4 af = *(const float4*)(qkc +
                            ((amt * 16 + sub * 8 + ksd)) * 128 + lane * 4);
                        uint2 bc[4];
                        #pragma unroll
                        for (int nt = 0; nt < 4; nt++) bc[nt] = bp[nt];
                        if (ksd < 7) {
                            #pragma unroll
                            for (int nt = 0; nt < 4; nt++)
                                bp[nt] = *(const uint2*)(wvb + nt * 4096 + (ksd + 1) * 64);
                        }
                        uint32_t a[4] = {f2u(af.x), f2u(af.y), f2u(af.z), f2u(af.w)};
                        #pragma unroll
                        for (int nt = 0; nt < 4; nt++)
                            mma_tf32(ovacc[nt], a, (const uint32_t*)&bc[nt]);
                    }
                }
                // lc STS
                #pragma unroll
                for (int it = 0; it < 4; it++) {
                    int i4 = tid + it * 512;
                    int j = i4 >> 4, dq = i4 & 15;
                    if (j < njc8) {
                        int hh = dq & 1;
                        int X = ((j & 7) ^ (hh << 2)) + (hh << 3);
                        float4 o;
                        o.x = to_tf32(sv[it].x); o.y = to_tf32(sv[it].y);
                        o.z = to_tf32(sv[it].z); o.w = to_tf32(sv[it].w);
                        *(float4*)(lc + ((j >> 3) * 16 + sub * 8 + (dq >> 1)) * 68 + X * 4) = o;
                    }
                }
            }
            __syncthreads();
        }

        // pl over both halves -> qkc
        #pragma unroll
        for (int sub = 0; sub < 2; sub++) {
            float placc[4][4];
            #pragma unroll
            for (int nt = 0; nt < 4; nt++)
                #pragma unroll
                for (int c = 0; c < 4; c++) placc[nt][c] = 0.f;
            for (int ksj = 0; ksj < T; ksj++) {
                float4 af = *(const float4*)(Pf + (amt * 16 + ksj) * 128 + lane * 4);
                uint32_t a[4] = {f2u(af.x), f2u(af.y), f2u(af.z), f2u(af.w)};
                #pragma unroll
                for (int nt = 0; nt < 4; nt++) {
                    int tb = (ksj * 16 + sub * 8 + anh * 4 + nt) * 68;
                    uint32_t bu[2] = { f2u(lc[tb + p2o0]), f2u(lc[tb + p2o1]) };
                    mma_tf32(placc[nt], a, bu);
                }
            }
            #pragma unroll
            for (int nt = 0; nt < 4; nt++) {
                int c0 = anh * 32 + nt * 8 + 2 * tg;
                #pragma unroll
                for (int e = 0; e < 4; e++) {
                    int c = c0 + (e & 1);
                    qkc[((amt * 16 + sub * 8 + (c >> 3)) * 32 + g * 4 + (c & 3)) * 4 +
                        ((e >> 1) + 2 * ((c >> 2) & 1))] = to_tf32(placc[nt][e]);
                }
            }
        }
        __syncthreads();
    }

    // ---- final ov (chunk order[3] = 2, both halves) ----
    #pragma unroll
    for (int sub = 0; sub < 2; sub++) {
        const int kkb = 2 * 16 + sub * 8;
        const float* wvb = g_Wvf + (size_t)(amt * 8 + anh * 4) * 4096 + kkb * 64 + lane * 2;
        uint2 bp[4];
        #pragma unroll
        for (int nt = 0; nt < 4; nt++) bp[nt] = *(const uint2*)(wvb + nt * 4096);
        #pragma unroll
        for (int ksd = 0; ksd < 8; ksd++) {
            float4 af = *(const float4*)(qkc + ((amt * 16 + sub * 8 + ksd)) * 128 + lane * 4);
            uint2 bc[4];
            #pragma unroll
            for (int nt = 0; nt < 4; nt++) bc[nt] = bp[nt];
            if (ksd < 7) {
                #pragma unroll
                for (int nt = 0; nt < 4; nt++)
                    bp[nt] = *(const uint2*)(wvb + nt * 4096 + (ksd + 1) * 64);
            }
            uint32_t a[4] = {f2u(af.x), f2u(af.y), f2u(af.z), f2u(af.w)};
            #pragma unroll
            for (int nt = 0; nt < 4; nt++)
                mma_tf32(ovacc[nt], a, (const uint32_t*)&bc[nt]);
        }
    }
    __syncthreads();   // all ov reads of qkc complete

    // ============ epilogue: ov -> a-frags, out = ov @ Wo^T + bo ============
    #pragma unroll
    for (int nt = 0; nt < 4; nt++) {
        int c0 = amt * 64 + anh * 32 + nt * 8 + 2 * tg;
        #pragma unroll
        for (int e = 0; e < 4; e++) {
            int r = g + ((e >> 1) << 3);          // token i
            int c = c0 + (e & 1);
            qkc[(c >> 3) * 128 + (g * 4 + (c & 3)) * 4 +
                ((r >> 3) + 2 * ((c >> 2) & 1))] = to_tf32(ovacc[nt][e]);
        }
    }
    __syncthreads();

    // O-proj
    {
        float acc[4][4];
        #pragma unroll
        for (int nt = 0; nt < 4; nt++)
            #pragma unroll
            for (int c = 0; c < 4; c++) acc[nt][c] = 0.f;
        const float* wob = g_Wof + ((size_t)(w * 4) * 64) * 64 + lane * 2;
        uint2 bp[4];
        #pragma unroll
        for (int nt = 0; nt < 4; nt++) bp[nt] = *(const uint2*)(wob + nt * 4096);
        for (int kk = 0; kk < 64; kk++) {
            float4 af = *(const float4*)(qkc + kk * 128 + lane * 4);
            uint32_t a[4] = {f2u(af.x), f2u(af.y), f2u(af.z), f2u(af.w)};
            uint2 bc[4];
            #pragma unroll
            for (int nt = 0; nt < 4; nt++) bc[nt] = bp[nt];
            if (kk < 63) {
                #pragma unroll
                for (int nt = 0; nt < 4; nt++)
                    bp[nt] = *(const uint2*)(wob + nt * 4096 + (kk + 1) * 64);
            }
            #pragma unroll
            for (int nt = 0; nt < 4; nt++)
                mma_tf32(acc[nt], a, (const uint32_t*)&bc[nt]);
        }
        #pragma unroll
        for (int nt = 0; nt < 4; nt++) {
            int c = w * 32 + nt * 8 + 2 * tg;
            float2 bb = *(const float2*)(bo + c);
            *(float2*)(out + ((size_t)(b * 16 + g)) * 512 + c) =
                make_float2(acc[nt][0] + bb.x, acc[nt][1] + bb.y);
            *(float2*)(out + ((size_t)(b * 16 + g + 8)) * 512 + c) =
                make_float2(acc[nt][2] + bb.x, acc[nt][3] + bb.y);
        }
    }
}

// ---------------------------------------------------------------------------
extern "C" void kernel_launch(void* const* d_in, const int* in_sizes, int n_in,
                              void* d_out, int out_size)
{
    const float* x  = (const float*)d_in[0];
    const float* l  = (const float*)d_in[1];
    const float* Wq = (const float*)d_in[2];
    const float* Wk = (const float*)d_in[3];
    const float* Wv = (const float*)d_in[4];
    const float* Wo = (const float*)d_in[5];
    const float* bo = (const float*)d_in[6];
    float* out = (float*)d_out;

    const int smem_f = F9_TOT * 4;           // 200704
    cudaFuncSetAttribute(fattn9, cudaFuncAttributeMaxDynamicSharedMemorySize, smem_f);

    prep_w<<<2048, 256>>>(Wq, Wk, Wv, Wo);
    fattn9<<<1024, 512, smem_f>>>(x, l, bo, out);
}